// round 1
// baseline (speedup 1.0000x reference)
#include <cuda_runtime.h>

// Problem constants (fixed by the reference)
#define NH  8      // heads
#define FD  128    // per-step feature dim
#define DQKD 128   // q/k dim per head
#define DVD 16     // v dim per head
#define LL  50     // sequence length
#define LP  64     // padded sequence length
#define XS  129    // smem stride for x and Y rows (conflict padding)
#define SS  65     // smem stride for S rows
#define VS  17     // smem stride for V rows

// Precomputed per-head folded weights (allocation-free scratch)
__device__ float g_A[NH][FD][FD];   // Wq @ Wk^T  (512 KB)
__device__ float g_u[NH][FD];       // Wq @ bk
__device__ float g_w[NH][FD];       // Wk @ bq
__device__ float g_c[NH];           // bq . bk

// ---------------------------------------------------------------------------
// Kernel 1: fold Q/K weights:  A = Wq Wk^T, u = Wq bk, w = Wk bq, c = bq.bk
// grid (8 heads, 8 slices), 256 threads
// ---------------------------------------------------------------------------
__global__ void precompute_kernel(const float* __restrict__ Wq,
                                  const float* __restrict__ bq,
                                  const float* __restrict__ Wk,
                                  const float* __restrict__ bk) {
    const int h     = blockIdx.x;
    const int slice = blockIdx.y;
    const int tid   = threadIdx.x;
    const float* wq = Wq + h * FD * DQKD;
    const float* wk = Wk + h * FD * DQKD;

    #pragma unroll
    for (int r = 0; r < 8; r++) {
        int o  = slice * 2048 + r * 256 + tid;
        int f  = o >> 7;
        int fp = o & 127;
        const float* qrow = wq + f * DQKD;
        const float* krow = wk + fp * DQKD;
        float acc = 0.f;
        #pragma unroll 8
        for (int e = 0; e < DQKD; e++) acc += qrow[e] * krow[e];
        g_A[h][f][fp] = acc;
    }
    if (slice == 0) {
        if (tid < FD) {
            float au = 0.f, aw = 0.f;
            #pragma unroll 8
            for (int e = 0; e < DQKD; e++) {
                au += wq[tid * DQKD + e] * bk[h * DQKD + e];
                aw += wk[tid * DQKD + e] * bq[h * DQKD + e];
            }
            g_u[h][tid] = au;
            g_w[h][tid] = aw;
        }
        if (tid == 128) {
            float c = 0.f;
            for (int e = 0; e < DQKD; e++) c += bq[h * DQKD + e] * bk[h * DQKD + e];
            g_c[h] = c;
        }
    }
}

// ---------------------------------------------------------------------------
// Kernel 2: fused attention, one CTA per batch row.
//   scores = x A x^T + p + r + c  -> leaky -> softmax over QUERY axis (cols)
//   out    = relu(att @ (x Wv + bv))
// ---------------------------------------------------------------------------
__global__ void __launch_bounds__(256, 2)
attn_main_kernel(const float* __restrict__ hid,
                 const float* __restrict__ Wv,
                 const float* __restrict__ bv,
                 float* __restrict__ out) {
    extern __shared__ float sm[];
    float* sx = sm;                    // [LP][XS]
    float* sY = sx + LP * XS;          // [LP][XS]
    float* sS = sY + LP * XS;          // [LP][SS]
    float* sV = sS + LP * SS;          // [LP][VS]
    float* sp = sV + LP * VS;          // [LP]
    float* sr = sp + LP;               // [LP]

    const int tid = threadIdx.x;
    const int b   = blockIdx.x;
    const float* xg = hid + (long long)b * (LL * FD);

    // load x, zero-pad rows [50,64)
    for (int i = tid; i < LP * FD; i += 256) {
        int l = i >> 7, f = i & 127;
        sx[l * XS + f] = (l < LL) ? xg[l * FD + f] : 0.f;
    }
    __syncthreads();

    const int te = (tid & 15) * 8;   // e-base for Y tile
    const int tl = (tid >> 4) * 4;   // l-base for Y and S tiles
    const int jm = (tid & 15) * 4;   // m-base for S tile

    for (int h = 0; h < NH; h++) {
        // ---- (a) Y = x @ A_h : 64x128, thread tile 4l x 8e ----
        {
            const float* Ah = &g_A[h][0][0];
            float acc[4][8];
            #pragma unroll
            for (int a = 0; a < 4; a++) {
                #pragma unroll
                for (int e = 0; e < 8; e++) acc[a][e] = 0.f;
            }
            #pragma unroll 2
            for (int f = 0; f < FD; f++) {
                float4 a0 = *(const float4*)(Ah + f * FD + te);
                float4 a1 = *(const float4*)(Ah + f * FD + te + 4);
                float av0 = a0.x, av1 = a0.y, av2 = a0.z, av3 = a0.w;
                float av4 = a1.x, av5 = a1.y, av6 = a1.z, av7 = a1.w;
                #pragma unroll
                for (int a = 0; a < 4; a++) {
                    float xv = sx[(tl + a) * XS + f];
                    acc[a][0] += xv * av0;  acc[a][1] += xv * av1;
                    acc[a][2] += xv * av2;  acc[a][3] += xv * av3;
                    acc[a][4] += xv * av4;  acc[a][5] += xv * av5;
                    acc[a][6] += xv * av6;  acc[a][7] += xv * av7;
                }
            }
            #pragma unroll
            for (int a = 0; a < 4; a++) {
                #pragma unroll
                for (int e = 0; e < 8; e++)
                    sY[(tl + a) * XS + te + e] = acc[a][e];
            }
        }
        // ---- (b) p[l] = x_l.u + c ;  r[m] = x_m.w ----
        if (tid < LP) {
            float acc = 0.f;
            if (tid < LL) {
                const float* xr = sx + tid * XS;
                acc = g_c[h];
                #pragma unroll 8
                for (int f = 0; f < FD; f++) acc += xr[f] * g_u[h][f];
            }
            sp[tid] = acc;
        } else if (tid < 2 * LP) {
            int m = tid - LP;
            float acc = 0.f;
            if (m < LL) {
                const float* xr = sx + m * XS;
                #pragma unroll 8
                for (int f = 0; f < FD; f++) acc += xr[f] * g_w[h][f];
            }
            sr[m] = acc;
        }
        __syncthreads();

        // ---- (c) S = Y x^T + p + r, leaky relu : 64x64, thread tile 4x4 ----
        {
            float acc[4][4];
            #pragma unroll
            for (int a = 0; a < 4; a++) {
                #pragma unroll
                for (int c2 = 0; c2 < 4; c2++) acc[a][c2] = 0.f;
            }
            #pragma unroll 2
            for (int f = 0; f < FD; f++) {
                float yv[4], xv[4];
                #pragma unroll
                for (int a = 0; a < 4; a++)  yv[a]  = sY[(tl + a) * XS + f];
                #pragma unroll
                for (int c2 = 0; c2 < 4; c2++) xv[c2] = sx[(jm + c2) * XS + f];
                #pragma unroll
                for (int a = 0; a < 4; a++) {
                    #pragma unroll
                    for (int c2 = 0; c2 < 4; c2++) acc[a][c2] += yv[a] * xv[c2];
                }
            }
            #pragma unroll
            for (int a = 0; a < 4; a++) {
                float pl = sp[tl + a];
                #pragma unroll
                for (int c2 = 0; c2 < 4; c2++) {
                    float v = acc[a][c2] + pl + sr[jm + c2];
                    v = v > 0.f ? v : 0.1f * v;
                    sS[(tl + a) * SS + jm + c2] = v;
                }
            }
        }
        __syncthreads();

        // ---- (d) softmax over l (column-wise), threads 0..49 own column m ----
        if (tid < LL) {
            const int m = tid;
            float mx = -1e30f;
            for (int l = 0; l < LL; l++) mx = fmaxf(mx, sS[l * SS + m]);
            float sum = 0.f;
            for (int l = 0; l < LL; l++) {
                float e = __expf(sS[l * SS + m] - mx);
                sS[l * SS + m] = e;
                sum += e;
            }
            float inv = 1.f / sum;
            for (int l = 0; l < LL; l++) sS[l * SS + m] *= inv;
        }
        // ---- (e) V = x @ Wv_h + bv (all threads, independent of (d)) ----
        for (int o = tid; o < LL * DVD; o += 256) {
            int l = o >> 4, dv = o & 15;
            float acc = bv[h * DVD + dv];
            const float* wv = Wv + h * FD * DVD + dv;
            const float* xr = sx + l * XS;
            #pragma unroll 8
            for (int f = 0; f < FD; f++) acc += xr[f] * wv[f * DVD];
            sV[l * VS + dv] = acc;
        }
        __syncthreads();

        // ---- (f) out = relu(att @ V), store this head's slice ----
        for (int o = tid; o < LL * DVD; o += 256) {
            int l = o >> 4, dv = o & 15;
            float acc = 0.f;
            const float* srow = sS + l * SS;
            const float* vcol = sV + dv;
            #pragma unroll 10
            for (int m = 0; m < LL; m++) acc += srow[m] * vcol[m * VS];
            acc = fmaxf(acc, 0.f);
            out[(long long)b * (LL * NH * DVD) + l * (NH * DVD) + h * DVD + dv] = acc;
        }
        __syncthreads();
    }
}

// ---------------------------------------------------------------------------
extern "C" void kernel_launch(void* const* d_in, const int* in_sizes, int n_in,
                              void* d_out, int out_size) {
    const float* hid = (const float*)d_in[0];
    const float* Wq  = (const float*)d_in[1];
    const float* bq  = (const float*)d_in[2];
    const float* Wk  = (const float*)d_in[3];
    const float* bk  = (const float*)d_in[4];
    const float* Wv  = (const float*)d_in[5];
    const float* bv  = (const float*)d_in[6];
    float* out = (float*)d_out;

    const int nb = in_sizes[0] / (LL * FD);

    const int smem_bytes = (2 * LP * XS + LP * SS + LP * VS + 2 * LP) * sizeof(float);
    cudaFuncSetAttribute(attn_main_kernel,
                         cudaFuncAttributeMaxDynamicSharedMemorySize, smem_bytes);

    precompute_kernel<<<dim3(NH, 8), 256>>>(Wq, bq, Wk, bk);
    attn_main_kernel<<<nb, 256, smem_bytes>>>(hid, Wv, bv, out);
}

// round 2
// speedup vs baseline: 1.1784x; 1.1784x over previous
#include <cuda_runtime.h>

// Problem constants (fixed by the reference)
#define NH   8     // heads
#define FD   128   // per-step feature dim
#define DQKD 128   // q/k dim per head
#define DVD  16    // v dim per head
#define LL   50    // sequence length
#define LP   64    // padded sequence length

#define XTS  68    // xT row stride (floats): [FD][XTS], conflict-free float4 rows
#define YS   132   // Y row stride (floats):  [LP][YS], row-major
#define STS_ 68    // ST row stride (floats): [LP][STS_], S transposed [m][l]
#define VSS  16    // V row stride (floats):  [LP][VSS]

// Precomputed per-head folded weights (allocation-free scratch)
__device__ float g_A[NH][FD][FD];   // Wq @ Wk^T
__device__ float g_u[NH][FD];       // Wq @ bk
__device__ float g_w[NH][FD];       // Wk @ bq
__device__ float g_c[NH];           // bq . bk

// ---------------------------------------------------------------------------
// Kernel 1: fold Q/K weights
// ---------------------------------------------------------------------------
__global__ void precompute_kernel(const float* __restrict__ Wq,
                                  const float* __restrict__ bq,
                                  const float* __restrict__ Wk,
                                  const float* __restrict__ bk) {
    const int h     = blockIdx.x;
    const int slice = blockIdx.y;
    const int tid   = threadIdx.x;
    const float* wq = Wq + h * FD * DQKD;
    const float* wk = Wk + h * FD * DQKD;

    #pragma unroll
    for (int r = 0; r < 8; r++) {
        int o  = slice * 2048 + r * 256 + tid;
        int f  = o >> 7;
        int fp = o & 127;
        const float* qrow = wq + f * DQKD;
        const float* krow = wk + fp * DQKD;
        float acc = 0.f;
        #pragma unroll 8
        for (int e = 0; e < DQKD; e++) acc += qrow[e] * krow[e];
        g_A[h][f][fp] = acc;
    }
    if (slice == 0) {
        if (tid < FD) {
            float au = 0.f, aw = 0.f;
            #pragma unroll 8
            for (int e = 0; e < DQKD; e++) {
                au += wq[tid * DQKD + e] * bk[h * DQKD + e];
                aw += wk[tid * DQKD + e] * bq[h * DQKD + e];
            }
            g_u[h][tid] = au;
            g_w[h][tid] = aw;
        }
        if (tid == 128) {
            float c = 0.f;
            for (int e = 0; e < DQKD; e++) c += bq[h * DQKD + e] * bk[h * DQKD + e];
            g_c[h] = c;
        }
    }
}

// ---------------------------------------------------------------------------
// Kernel 2: fused attention, one CTA per batch row, float4 everywhere.
// ---------------------------------------------------------------------------
__global__ void __launch_bounds__(256, 2)
attn_main_kernel(const float* __restrict__ hid,
                 const float* __restrict__ Wv,
                 const float* __restrict__ bv,
                 float* __restrict__ out) {
    extern __shared__ float sm[];
    float* xT = sm;                      // [FD][XTS]   x transposed: xT[f][l]
    float* sY = xT + FD * XTS;           // [LP][YS]    Y row-major
    float* sT = sY + LP * YS;            // [LP][STS_]  S transposed: sT[m][l]
    float* sV = sT + LP * STS_;          // [LP][VSS]
    float* sp = sV + LP * VSS;           // [LP]
    float* sr = sp + LP;                 // [LP]

    const int tid = threadIdx.x;
    const int b   = blockIdx.x;
    const float* xg = hid + (long long)b * (LL * FD);

    // load + transpose x into xT[f][l], zero-pad l in [50,64)
    for (int i = tid; i < LP * FD; i += 256) {
        int l = i >> 7, f = i & 127;
        xT[f * XTS + l] = (l < LL) ? xg[l * FD + f] : 0.f;
    }
    __syncthreads();

    const int te  = (tid & 15) * 8;   // e-base (stage a)
    const int tl  = (tid >> 4) * 4;   // l-base (stages a, c)
    const int jm  = (tid & 15) * 4;   // m-base (stage c)
    const int fl  = tid >> 2;         // l for stages e/f (0..63)
    const int dvb = (tid & 3) * 4;    // dv base for stages e/f

    for (int h = 0; h < NH; h++) {
        // ---- (a) Y = x @ A_h : 64x128, thread tile 4l x 8e, f-reduction ----
        {
            const float* Ah = &g_A[h][0][0];
            float acc[4][8];
            #pragma unroll
            for (int a = 0; a < 4; a++)
                #pragma unroll
                for (int e = 0; e < 8; e++) acc[a][e] = 0.f;

            #pragma unroll 4
            for (int f = 0; f < FD; f++) {
                float4 xv = *(const float4*)(xT + f * XTS + tl);
                float4 a0 = *(const float4*)(Ah + f * FD + te);
                float4 a1 = *(const float4*)(Ah + f * FD + te + 4);
                const float xa[4] = {xv.x, xv.y, xv.z, xv.w};
                #pragma unroll
                for (int a = 0; a < 4; a++) {
                    acc[a][0] += xa[a] * a0.x;  acc[a][1] += xa[a] * a0.y;
                    acc[a][2] += xa[a] * a0.z;  acc[a][3] += xa[a] * a0.w;
                    acc[a][4] += xa[a] * a1.x;  acc[a][5] += xa[a] * a1.y;
                    acc[a][6] += xa[a] * a1.z;  acc[a][7] += xa[a] * a1.w;
                }
            }
            #pragma unroll
            for (int a = 0; a < 4; a++) {
                float4 s0 = make_float4(acc[a][0], acc[a][1], acc[a][2], acc[a][3]);
                float4 s1 = make_float4(acc[a][4], acc[a][5], acc[a][6], acc[a][7]);
                *(float4*)(sY + (tl + a) * YS + te)     = s0;
                *(float4*)(sY + (tl + a) * YS + te + 4) = s1;
            }
        }
        // ---- (b) p[l] = x_l.u + c ;  r[m] = x_m.w ----
        if (tid < LP) {
            const int l = tid;
            float acc = g_c[h];
            #pragma unroll 8
            for (int f = 0; f < FD; f++) acc += xT[f * XTS + l] * g_u[h][f];
            sp[l] = acc;
        } else if (tid < 2 * LP) {
            const int m = tid - LP;
            float acc = 0.f;
            #pragma unroll 8
            for (int f = 0; f < FD; f++) acc += xT[f * XTS + m] * g_w[h][f];
            sr[m] = acc;
        }
        __syncthreads();

        // ---- (c) S = Y x^T + p + r, leaky; store transposed sT[m][l] ----
        {
            float acc[4][4];
            #pragma unroll
            for (int a = 0; a < 4; a++)
                #pragma unroll
                for (int c2 = 0; c2 < 4; c2++) acc[a][c2] = 0.f;

            #pragma unroll 2
            for (int e = 0; e < FD; e += 4) {
                float4 yv[4], xv[4];
                #pragma unroll
                for (int a = 0; a < 4; a++)
                    yv[a] = *(const float4*)(sY + (tl + a) * YS + e);
                #pragma unroll
                for (int q = 0; q < 4; q++)
                    xv[q] = *(const float4*)(xT + (e + q) * XTS + jm);
                #pragma unroll
                for (int a = 0; a < 4; a++) {
                    acc[a][0] += yv[a].x * xv[0].x + yv[a].y * xv[1].x
                               + yv[a].z * xv[2].x + yv[a].w * xv[3].x;
                    acc[a][1] += yv[a].x * xv[0].y + yv[a].y * xv[1].y
                               + yv[a].z * xv[2].y + yv[a].w * xv[3].y;
                    acc[a][2] += yv[a].x * xv[0].z + yv[a].y * xv[1].z
                               + yv[a].z * xv[2].z + yv[a].w * xv[3].z;
                    acc[a][3] += yv[a].x * xv[0].w + yv[a].y * xv[1].w
                               + yv[a].z * xv[2].w + yv[a].w * xv[3].w;
                }
            }
            float pl[4];
            #pragma unroll
            for (int a = 0; a < 4; a++) pl[a] = sp[tl + a];
            #pragma unroll
            for (int c2 = 0; c2 < 4; c2++) {
                float rm = sr[jm + c2];
                float4 w;
                float v0 = acc[0][c2] + pl[0] + rm;
                float v1 = acc[1][c2] + pl[1] + rm;
                float v2 = acc[2][c2] + pl[2] + rm;
                float v3 = acc[3][c2] + pl[3] + rm;
                w.x = v0 > 0.f ? v0 : 0.1f * v0;
                w.y = v1 > 0.f ? v1 : 0.1f * v1;
                w.z = v2 > 0.f ? v2 : 0.1f * v2;
                w.w = v3 > 0.f ? v3 : 0.1f * v3;
                *(float4*)(sT + (jm + c2) * STS_ + tl) = w;
            }
        }
        __syncthreads();

        // ---- (d) softmax over l (rows of sT), thread m owns row m ----
        if (tid < LL) {
            float* row = sT + tid * STS_;
            float mx = -1e30f;
            #pragma unroll 10
            for (int l = 0; l < LL; l++) mx = fmaxf(mx, row[l]);
            float sum = 0.f;
            #pragma unroll 10
            for (int l = 0; l < LL; l++) {
                float e = __expf(row[l] - mx);
                row[l] = e;
                sum += e;
            }
            float inv = 1.f / sum;
            #pragma unroll 10
            for (int l = 0; l < LL; l++) row[l] *= inv;
        }
        // ---- (e) V = x @ Wv_h + bv (independent of softmax) ----
        {
            const float* wvh = Wv + h * FD * DVD;
            float4 acc = *(const float4*)(bv + h * DVD + dvb);
            #pragma unroll 4
            for (int f = 0; f < FD; f++) {
                float xs = xT[f * XTS + fl];
                float4 wv = *(const float4*)(wvh + f * DVD + dvb);
                acc.x += xs * wv.x;  acc.y += xs * wv.y;
                acc.z += xs * wv.z;  acc.w += xs * wv.w;
            }
            *(float4*)(sV + fl * VSS + dvb) = acc;
        }
        __syncthreads();

        // ---- (f) out = relu(att @ V), att[l][m] = sT[m][l] ----
        if (fl < LL) {
            float4 acc = make_float4(0.f, 0.f, 0.f, 0.f);
            #pragma unroll 10
            for (int m = 0; m < LL; m++) {
                float s = sT[m * STS_ + fl];
                float4 vv = *(const float4*)(sV + m * VSS + dvb);
                acc.x += s * vv.x;  acc.y += s * vv.y;
                acc.z += s * vv.z;  acc.w += s * vv.w;
            }
            acc.x = fmaxf(acc.x, 0.f);  acc.y = fmaxf(acc.y, 0.f);
            acc.z = fmaxf(acc.z, 0.f);  acc.w = fmaxf(acc.w, 0.f);
            *(float4*)(out + (long long)b * (LL * NH * DVD)
                           + fl * (NH * DVD) + h * DVD + dvb) = acc;
        }
        __syncthreads();
    }
}

// ---------------------------------------------------------------------------
extern "C" void kernel_launch(void* const* d_in, const int* in_sizes, int n_in,
                              void* d_out, int out_size) {
    const float* hid = (const float*)d_in[0];
    const float* Wq  = (const float*)d_in[1];
    const float* bq  = (const float*)d_in[2];
    const float* Wk  = (const float*)d_in[3];
    const float* bk  = (const float*)d_in[4];
    const float* Wv  = (const float*)d_in[5];
    const float* bv  = (const float*)d_in[6];
    float* out = (float*)d_out;

    const int nb = in_sizes[0] / (LL * FD);

    const int smem_bytes =
        (FD * XTS + LP * YS + LP * STS_ + LP * VSS + 2 * LP) * sizeof(float);
    cudaFuncSetAttribute(attn_main_kernel,
                         cudaFuncAttributeMaxDynamicSharedMemorySize, smem_bytes);

    precompute_kernel<<<dim3(NH, 8), 256>>>(Wq, bq, Wk, bk);
    attn_main_kernel<<<nb, 256, smem_bytes>>>(hid, Wv, bv, out);
}